// round 1
// baseline (speedup 1.0000x reference)
#include <cuda_runtime.h>

#define NV 32
#define N2 1024
#define N3 32768
#define N4 1048576
#define MB 16   // n*d = 2*8
#define DD 8
#define SOUT 8

// Scratch (static device memory; no allocation).
// r3 order (kept axes A): 0=(i,j,k) 1=(i,j,l) 2=(i,k,l) 3=(j,k,l)
__device__ __align__(16) float g_r3[4][MB][N3];
// r2 order: 0=(i,j) 1=(i,k) 2=(i,l) 3=(j,k) 4=(j,l) 5=(k,l)
__device__ __align__(16) float g_r2[6][MB][N2];
// r1 order: 0=i 1=j 2=k 3=l
__device__ __align__(16) float g_r1[4][MB][NV];
// channel-mixed, B-grouped tensors (same subset ordering as above)
__device__ __align__(16) float g_g3[4][2][SOUT][N3];
__device__ __align__(16) float g_g2[6][2][SOUT][N2];
__device__ __align__(16) float g_g1[4][2][SOUT][NV];

// ---------------------------------------------------------------------------
// K1: block per (m,i). One pass over x[m,i,:,:,:] producing:
//   r_ijk (sum over l), r_ijl (sum over k), r_ikl (sum over j)
// ---------------------------------------------------------------------------
__global__ void __launch_bounds__(256) k_reduce_a(const float* __restrict__ x) {
    int m = blockIdx.x >> 5;
    int i = blockIdx.x & 31;
    int t = threadIdx.x;              // 0..255
    int k = t >> 3;                   // 0..31
    int w = t >> 5, lane = t & 31;
    __shared__ float sp[8][33];

    float4 acc; acc.x = acc.y = acc.z = acc.w = 0.f;
    const float4* xb = reinterpret_cast<const float4*>(x) + (size_t)(m * NV + i) * (N3 / 4);

    for (int j = 0; j < 32; j++) {
        float4 v = __ldg(xb + j * 256 + t);   // plane element (k, l4) == t
        acc.x += v.x; acc.y += v.y; acc.z += v.z; acc.w += v.w;

        // r_ijk: sum over l within row k (groups of 8 lanes share k)
        float s = v.x + v.y + v.z + v.w;
        s += __shfl_down_sync(0xffffffffu, s, 4, 8);
        s += __shfl_down_sync(0xffffffffu, s, 2, 8);
        s += __shfl_down_sync(0xffffffffu, s, 1, 8);
        if ((lane & 7) == 0) g_r3[0][m][i * N2 + j * 32 + k] = s;

        // r_ijl: sum over k. Reduce the warp's 4 k-rows (lanes lq, lq+8, lq+16, lq+24)
        float px = v.x, py = v.y, pz = v.z, pw = v.w;
        px += __shfl_down_sync(0xffffffffu, px, 16);
        py += __shfl_down_sync(0xffffffffu, py, 16);
        pz += __shfl_down_sync(0xffffffffu, pz, 16);
        pw += __shfl_down_sync(0xffffffffu, pw, 16);
        px += __shfl_down_sync(0xffffffffu, px, 8);
        py += __shfl_down_sync(0xffffffffu, py, 8);
        pz += __shfl_down_sync(0xffffffffu, pz, 8);
        pw += __shfl_down_sync(0xffffffffu, pw, 8);
        if (lane < 8) {
            sp[w][lane * 4 + 0] = px;
            sp[w][lane * 4 + 1] = py;
            sp[w][lane * 4 + 2] = pz;
            sp[w][lane * 4 + 3] = pw;
        }
        __syncthreads();
        if (t < 32) {
            float s2 = sp[0][t] + sp[1][t] + sp[2][t] + sp[3][t]
                     + sp[4][t] + sp[5][t] + sp[6][t] + sp[7][t];
            g_r3[1][m][i * N2 + j * 32 + t] = s2;
        }
        __syncthreads();
    }
    // r_ikl complete for this (m,i): sum over all j accumulated in registers
    reinterpret_cast<float4*>(g_r3[2][m])[i * 256 + t] = acc;
}

// ---------------------------------------------------------------------------
// K2: r_jkl = sum over i. Thread per (m,j,k,l4). Coalesced strided reads.
// ---------------------------------------------------------------------------
__global__ void __launch_bounds__(256) k_reduce_b(const float* __restrict__ x) {
    int g = blockIdx.x * 256 + threadIdx.x;   // 0..131071
    int lq = g & 7, k = (g >> 3) & 31, j = (g >> 8) & 31, m = g >> 13;
    const float4* xb = reinterpret_cast<const float4*>(x);
    size_t off = (size_t)m * (N4 / 4) + j * 256 + k * 8 + lq;
    float4 acc; acc.x = acc.y = acc.z = acc.w = 0.f;
#pragma unroll
    for (int i = 0; i < 32; i++) {
        float4 v = __ldg(xb + off + (size_t)i * (N3 / 4));
        acc.x += v.x; acc.y += v.y; acc.z += v.z; acc.w += v.w;
    }
    reinterpret_cast<float4*>(g_r3[3][m])[j * 256 + k * 8 + lq] = acc;
}

// ---------------------------------------------------------------------------
// K3: six rank-2 reductions from r3. Thread per (z-selected) output element.
// ---------------------------------------------------------------------------
__global__ void __launch_bounds__(256) k_r2k(void) {
    int b = blockIdx.x;
    int z = b >> 6;                         // 0..5
    int r = (b & 63) * 256 + threadIdx.x;   // 0..16383
    int m = r >> 10, tt = r & 1023, a = tt >> 5, c = tt & 31;

    int src, strd, off;
    switch (z) {
        case 0: src = 0; strd = 1;    off = a * N2 + c * 32; break; // r_ij = sum_k r_ijk
        case 1: src = 0; strd = 32;   off = a * N2 + c;      break; // r_ik = sum_j r_ijk
        case 2: src = 1; strd = 32;   off = a * N2 + c;      break; // r_il = sum_j r_ijl
        case 3: src = 0; strd = N2;   off = a * 32 + c;      break; // r_jk = sum_i r_ijk
        case 4: src = 1; strd = N2;   off = a * 32 + c;      break; // r_jl = sum_i r_ijl
        default: src = 2; strd = N2;  off = a * 32 + c;      break; // r_kl = sum_i r_ikl
    }
    const float* p = g_r3[src][m] + off;
    float s = 0.f;
#pragma unroll
    for (int u = 0; u < 32; u++) s += __ldg(p + u * strd);
    g_r2[z][m][tt] = s;
}

// ---------------------------------------------------------------------------
// K4: four rank-1 reductions from r2.
// ---------------------------------------------------------------------------
__global__ void __launch_bounds__(256) k_r1k(void) {
    int g = blockIdx.x * 256 + threadIdx.x;   // 0..2047
    int z = g >> 9, m = (g >> 5) & 15, v = g & 31;
    float s = 0.f;
    if (z == 0) {           // r_i = sum_j r_ij
#pragma unroll
        for (int u = 0; u < 32; u++) s += g_r2[0][m][v * 32 + u];
    } else if (z == 1) {    // r_j = sum_i r_ij
#pragma unroll
        for (int u = 0; u < 32; u++) s += g_r2[0][m][u * 32 + v];
    } else if (z == 2) {    // r_k = sum_j r_jk
#pragma unroll
        for (int u = 0; u < 32; u++) s += g_r2[3][m][u * 32 + v];
    } else {                // r_l = sum_k r_kl
#pragma unroll
        for (int u = 0; u < 32; u++) s += g_r2[5][m][u * 32 + v];
    }
    g_r1[z][m][v] = s;
}

// ---------------------------------------------------------------------------
// K5: g3_B[n,so,t] = sum_{A,d} coef[d,so,52+A*4+B] * r3_A[n,d,t]
// ---------------------------------------------------------------------------
__global__ void __launch_bounds__(256) k_g3(const float* __restrict__ coefs) {
    __shared__ float C[4][4][64];   // [A][B][d*8+so]
    int t = threadIdx.x;
    for (int e = t; e < 1024; e += 256) {
        int a = e >> 8, b = (e >> 6) & 3, ds = e & 63;
        int d = ds >> 3, so = ds & 7;
        C[a][b][ds] = coefs[d * 552 + so * 69 + 52 + a * 4 + b];
    }
    __syncthreads();

    int gid = blockIdx.x * 256 + t;
    int n = gid >> 15, tt = gid & 32767;

    float acc[32];
#pragma unroll
    for (int q = 0; q < 32; q++) acc[q] = 0.f;

#pragma unroll
    for (int a = 0; a < 4; a++) {
        float vd[8];
#pragma unroll
        for (int d = 0; d < 8; d++) vd[d] = g_r3[a][n * 8 + d][tt];
#pragma unroll
        for (int b = 0; b < 4; b++)
#pragma unroll
            for (int so = 0; so < 8; so++) {
                float s = 0.f;
#pragma unroll
                for (int d = 0; d < 8; d++) s += C[a][b][d * 8 + so] * vd[d];
                acc[b * 8 + so] += s;
            }
    }
#pragma unroll
    for (int b = 0; b < 4; b++)
#pragma unroll
        for (int so = 0; so < 8; so++)
            g_g3[b][n][so][tt] = acc[b * 8 + so];
}

// ---------------------------------------------------------------------------
// K6: g2 (blocks 0..7) and g1 (block 8)
// ---------------------------------------------------------------------------
__global__ void __launch_bounds__(256) k_g21(const float* __restrict__ coefs) {
    __shared__ float C2[6][6][64];
    __shared__ float C1[4][4][64];
    int t = threadIdx.x;
    if (blockIdx.x < 8) {
        for (int e = t; e < 2304; e += 256) {
            int a = e / 384;
            int rem = e - a * 384;
            int b = rem >> 6, ds = rem & 63;
            int d = ds >> 3, so = ds & 7;
            C2[a][b][ds] = coefs[d * 552 + so * 69 + 16 + a * 6 + b];
        }
        __syncthreads();
        int r = blockIdx.x * 256 + t;
        int n = r >> 10, tt = r & 1023;
        float acc[48];
#pragma unroll
        for (int q = 0; q < 48; q++) acc[q] = 0.f;
#pragma unroll
        for (int a = 0; a < 6; a++) {
            float vd[8];
#pragma unroll
            for (int d = 0; d < 8; d++) vd[d] = g_r2[a][n * 8 + d][tt];
#pragma unroll
            for (int b = 0; b < 6; b++)
#pragma unroll
                for (int so = 0; so < 8; so++) {
                    float s = 0.f;
#pragma unroll
                    for (int d = 0; d < 8; d++) s += C2[a][b][d * 8 + so] * vd[d];
                    acc[b * 8 + so] += s;
                }
        }
#pragma unroll
        for (int b = 0; b < 6; b++)
#pragma unroll
            for (int so = 0; so < 8; so++)
                g_g2[b][n][so][tt] = acc[b * 8 + so];
    } else {
        for (int e = t; e < 1024; e += 256) {
            int a = e >> 8, b = (e >> 6) & 3, ds = e & 63;
            int d = ds >> 3, so = ds & 7;
            C1[a][b][ds] = coefs[d * 552 + so * 69 + a * 4 + b];
        }
        __syncthreads();
        if (t < 64) {
            int n = t >> 5, v = t & 31;
            float acc[32];
#pragma unroll
            for (int q = 0; q < 32; q++) acc[q] = 0.f;
#pragma unroll
            for (int a = 0; a < 4; a++) {
                float vd[8];
#pragma unroll
                for (int d = 0; d < 8; d++) vd[d] = g_r1[a][n * 8 + d][v];
#pragma unroll
                for (int b = 0; b < 4; b++)
#pragma unroll
                    for (int so = 0; so < 8; so++) {
                        float s = 0.f;
#pragma unroll
                        for (int d = 0; d < 8; d++) s += C1[a][b][d * 8 + so] * vd[d];
                        acc[b * 8 + so] += s;
                    }
            }
#pragma unroll
            for (int b = 0; b < 4; b++)
#pragma unroll
                for (int so = 0; so < 8; so++)
                    g_g1[b][n][so][v] = acc[b * 8 + so];
        }
    }
}

// ---------------------------------------------------------------------------
// K7: final assembly. Block per (n,i,j); thread per (k, l4).
// out = P[so][k] + Q[so][l] + g3_ikl + g3_jkl + g2_kl + sum_d c4[d,so]*x
// ---------------------------------------------------------------------------
__global__ void __launch_bounds__(256) k_final(const float* __restrict__ x,
                                               const float* __restrict__ coefs,
                                               const float* __restrict__ bias,
                                               float* __restrict__ out) {
    int bid = blockIdx.x;
    int n = bid >> 10, i = (bid >> 5) & 31, j = bid & 31;
    int t = threadIdx.x;
    int k = t >> 3, lq = t & 7;

    __shared__ float P[8][32], Q[8][32], cf[8][8];
    if (t < 64) {
        int d = t >> 3, so = t & 7;
        cf[d][so] = coefs[d * 552 + so * 69 + 68];
    }
    {
        int so = t >> 5, kk = t & 31;
        int ij = i * 32 + j;
        P[so][kk] = g_g3[0][n][so][ij * 32 + kk]
                  + g_g2[1][n][so][i * 32 + kk]
                  + g_g2[3][n][so][j * 32 + kk]
                  + g_g1[2][n][so][kk]
                  + g_g2[0][n][so][ij]
                  + g_g1[0][n][so][i]
                  + g_g1[1][n][so][j]
                  + bias[so];
        Q[so][kk] = g_g3[1][n][so][ij * 32 + kk]
                  + g_g2[2][n][so][i * 32 + kk]
                  + g_g2[4][n][so][j * 32 + kk]
                  + g_g1[3][n][so][kk];
    }
    __syncthreads();

    int plane = (i * 32 + j) * 256 + t;     // float4 index inside one N^4 slice
    int kl = k * 8 + lq;                    // float4 index inside one N^2 block
    const float4* xb = reinterpret_cast<const float4*>(x);
    float4* ob = reinterpret_cast<float4*>(out);

    float4 xv[8];
#pragma unroll
    for (int d = 0; d < 8; d++)
        xv[d] = __ldg(xb + (size_t)(n * 8 + d) * (N4 / 4) + plane);

#pragma unroll
    for (int so = 0; so < 8; so++) {
        float4 a2 = reinterpret_cast<const float4*>(g_g2[5][n][so])[kl];
        float4 a3 = reinterpret_cast<const float4*>(g_g3[2][n][so])[i * 256 + kl];
        float4 a4 = reinterpret_cast<const float4*>(g_g3[3][n][so])[j * 256 + kl];
        float base = P[so][k];
        float4 q = *reinterpret_cast<const float4*>(&Q[so][lq * 4]);

        float4 acc;
        acc.x = base + q.x + a2.x + a3.x + a4.x;
        acc.y = base + q.y + a2.y + a3.y + a4.y;
        acc.z = base + q.z + a2.z + a3.z + a4.z;
        acc.w = base + q.w + a2.w + a3.w + a4.w;
#pragma unroll
        for (int d = 0; d < 8; d++) {
            float c = cf[d][so];
            acc.x += c * xv[d].x;
            acc.y += c * xv[d].y;
            acc.z += c * xv[d].z;
            acc.w += c * xv[d].w;
        }
        ob[(size_t)(n * 8 + so) * (N4 / 4) + plane] = acc;
    }
}

extern "C" void kernel_launch(void* const* d_in, const int* in_sizes, int n_in,
                              void* d_out, int out_size) {
    const float* x     = (const float*)d_in[0];
    const float* coefs = (const float*)d_in[1];
    const float* bias  = (const float*)d_in[2];
    float* out = (float*)d_out;

    k_reduce_a<<<512, 256>>>(x);     // r_ijk, r_ijl, r_ikl
    k_reduce_b<<<512, 256>>>(x);     // r_jkl
    k_r2k<<<384, 256>>>();           // six rank-2 reductions
    k_r1k<<<8, 256>>>();             // four rank-1 reductions
    k_g3<<<256, 256>>>(coefs);       // channel-mixed rank-3 B-groups
    k_g21<<<9, 256>>>(coefs);        // channel-mixed rank-2 and rank-1 B-groups
    k_final<<<2048, 256>>>(x, coefs, bias, out);
}

// round 2
// speedup vs baseline: 1.1227x; 1.1227x over previous
#include <cuda_runtime.h>

#define NV 32
#define N2 1024
#define N3 32768
#define N4 1048576
#define MB 16   // n*d = 2*8
#define SOUT 8

// Scratch (static device memory; no allocation).
// r3 kept-axes order: 0=(i,j,k) 1=(i,j,l) 2=(i,k,l) 3=(j,k,l)
__device__ __align__(16) float g_r3[4][MB][N3];
// r2 order: 0=(i,j) 1=(i,k) 2=(i,l) 3=(j,k) 4=(j,l) 5=(k,l)
__device__ __align__(16) float g_r2[6][MB][N2];
// channel-mixed B-grouped tables
__device__ __align__(16) float g_g3[4][2][SOUT][N3];
__device__ __align__(16) float g_g2[6][2][SOUT][N2];
__device__ __align__(16) float g_g1[4][2][SOUT][NV];
// V1[n][so][i*1024 + k*32 + l] = g3_ikl + g2_kl  (merged table)
__device__ __align__(16) float g_V1[2][SOUT][N3];

// ---------------------------------------------------------------------------
// K1: block per (m,i). ONE pass over x[m,i,:,:,:], ONE __syncthreads.
// Produces r3[0]=r_ijk, r3[1]=r_ijl, r3[2]=r_ikl, r2[0]=r_ij, r2[1]=r_ik.
// ---------------------------------------------------------------------------
__global__ void __launch_bounds__(256) k_pass1(const float* __restrict__ x) {
    int m = blockIdx.x >> 5, i = blockIdx.x & 31;
    int t = threadIdx.x, w = t >> 5, lane = t & 31;
    int l4 = lane & 7;

    __shared__ float4 scol[8][32][8];   // [w][j][l4] per-warp column partials (32KB)
    __shared__ float  srow[32][32];     // [j][k] row sums (4KB)
    __shared__ float  sij[32][8];       // [j][w] plane partials (1KB)

    float4 acc; acc.x = acc.y = acc.z = acc.w = 0.f;
    float accIK = 0.f;
    const float4* xb = reinterpret_cast<const float4*>(x) + (size_t)(m * 32 + i) * (N3 / 4);

    for (int jo = 0; jo < 32; jo += 4) {
        float4 vv[4];
#pragma unroll
        for (int u = 0; u < 4; ++u) vv[u] = __ldg(xb + (jo + u) * 256 + t);
#pragma unroll
        for (int u = 0; u < 4; ++u) {
            int j = jo + u;
            float4 v = vv[u];
            acc.x += v.x; acc.y += v.y; acc.z += v.z; acc.w += v.w;

            // row sum over l (8-lane groups share one k)
            float s = v.x + v.y + v.z + v.w;
            s += __shfl_down_sync(0xffffffffu, s, 4, 8);
            s += __shfl_down_sync(0xffffffffu, s, 2, 8);
            s += __shfl_down_sync(0xffffffffu, s, 1, 8);
            if (l4 == 0) { srow[j][t >> 3] = s; accIK += s; }

            // plane partial (per warp): sum the 4 row sums (lanes 0,8,16,24)
            float p = s;
            p += __shfl_down_sync(0xffffffffu, p, 16);
            p += __shfl_down_sync(0xffffffffu, p, 8);
            if (lane == 0) sij[j][w] = p;

            // column partial: sum over this warp's 4 k values (lane bits 3..4)
            float4 c = v;
            c.x += __shfl_xor_sync(0xffffffffu, c.x, 8);
            c.y += __shfl_xor_sync(0xffffffffu, c.y, 8);
            c.z += __shfl_xor_sync(0xffffffffu, c.z, 8);
            c.w += __shfl_xor_sync(0xffffffffu, c.w, 8);
            c.x += __shfl_xor_sync(0xffffffffu, c.x, 16);
            c.y += __shfl_xor_sync(0xffffffffu, c.y, 16);
            c.z += __shfl_xor_sync(0xffffffffu, c.z, 16);
            c.w += __shfl_xor_sync(0xffffffffu, c.w, 16);
            if (lane < 8) scol[w][j][lane] = c;
        }
    }
    __syncthreads();

    // r_ikl (complete: summed over j in registers)
    reinterpret_cast<float4*>(g_r3[2][m])[i * 256 + t] = acc;
    // r_ijk from srow (coalesced)
    reinterpret_cast<float4*>(g_r3[0][m] + i * N2)[t] = reinterpret_cast<float4*>(srow)[t];
    // r_ijl: combine the 8 per-warp column partials
    {
        int j = t >> 3, q = t & 7;
        float4 rv = scol[0][j][q];
#pragma unroll
        for (int ww = 1; ww < 8; ++ww) {
            float4 cc = scol[ww][j][q];
            rv.x += cc.x; rv.y += cc.y; rv.z += cc.z; rv.w += cc.w;
        }
        reinterpret_cast<float4*>(g_r3[1][m] + i * N2)[t] = rv;
    }
    // r_ij
    if (t < 32) {
        float s = 0.f;
#pragma unroll
        for (int ww = 0; ww < 8; ++ww) s += sij[t][ww];
        g_r2[0][m][i * 32 + t] = s;
    }
    // r_ik
    if (l4 == 0) g_r2[1][m][i * 32 + (t >> 3)] = accIK;
}

// ---------------------------------------------------------------------------
// K2: second x pass. Thread per (n, tt=(j,k,l)). Computes r_jkl on the fly,
// writes it raw, and produces ALL FOUR g3 tables (channel mix) in one shot.
// ---------------------------------------------------------------------------
__global__ void __launch_bounds__(256) k_pass2(const float* __restrict__ x,
                                               const float* __restrict__ coefs) {
    __shared__ float C[4][4][64];   // [A][B][d*8+so]
    int t = threadIdx.x;
    for (int e = t; e < 1024; e += 256) {
        int a = e >> 8, b = (e >> 6) & 3, ds = e & 63;
        int d = ds >> 3, so = ds & 7;
        C[a][b][ds] = coefs[d * 552 + so * 69 + 52 + a * 4 + b];
    }
    __syncthreads();

    int g = blockIdx.x * 256 + t;
    int n = g >> 15, tt = g & 32767;
    const float* xb = x + (size_t)n * 8 * N4 + tt;

    float rj[8];
#pragma unroll
    for (int d = 0; d < 8; ++d) rj[d] = 0.f;
#pragma unroll 4
    for (int i = 0; i < 32; ++i) {
#pragma unroll
        for (int d = 0; d < 8; ++d)
            rj[d] += __ldg(xb + (size_t)d * N4 + i * N3);
    }
#pragma unroll
    for (int d = 0; d < 8; ++d) g_r3[3][n * 8 + d][tt] = rj[d];

    float acc[32];
#pragma unroll
    for (int q = 0; q < 32; ++q) acc[q] = 0.f;
#pragma unroll
    for (int a = 0; a < 4; ++a) {
        float vd[8];
#pragma unroll
        for (int d = 0; d < 8; ++d)
            vd[d] = (a == 3) ? rj[d] : __ldg(&g_r3[a][n * 8 + d][tt]);
#pragma unroll
        for (int b = 0; b < 4; ++b)
#pragma unroll
            for (int so = 0; so < 8; ++so) {
                float s = 0.f;
#pragma unroll
                for (int d = 0; d < 8; ++d) s += C[a][b][d * 8 + so] * vd[d];
                acc[b * 8 + so] += s;
            }
    }
#pragma unroll
    for (int b = 0; b < 4; ++b)
#pragma unroll
        for (int so = 0; so < 8; ++so)
            g_g3[b][n][so][tt] = acc[b * 8 + so];
}

// ---------------------------------------------------------------------------
// S1: remaining rank-2 reductions: r_il (from r3[1]), r_jk/r_jl/r_kl (from r3[3])
// ---------------------------------------------------------------------------
__global__ void __launch_bounds__(256) k_small1(void) {
    int g = blockIdx.x * 256 + threadIdx.x;     // 0..65535
    int z = g >> 14, r = g & 16383;
    int m = r >> 10, tt = r & 1023, a = tt >> 5, c = tt & 31;

    const float* p; int strd;
    switch (z) {
        case 0:  p = g_r3[1][m] + a * N2 + c;      strd = 32;   break;  // r_il
        case 1:  p = g_r3[3][m] + a * N2 + c * 32; strd = 1;    break;  // r_jk
        case 2:  p = g_r3[3][m] + a * N2 + c;      strd = 32;   break;  // r_jl
        default: p = g_r3[3][m] + a * 32 + c;      strd = N2;   break;  // r_kl
    }
    float s = 0.f;
#pragma unroll
    for (int u = 0; u < 32; ++u) s += __ldg(p + u * strd);
    g_r2[z + 2][m][tt] = s;
}

// ---------------------------------------------------------------------------
// S2: blocks 0..7: g2 mix (+ fold g2_kl into g3_ikl -> V1); block 8: r1 + g1.
// ---------------------------------------------------------------------------
__global__ void __launch_bounds__(256) k_small2(const float* __restrict__ coefs) {
    int t = threadIdx.x;
    if (blockIdx.x < 8) {
        __shared__ float C2[6][6][64];
        for (int e = t; e < 2304; e += 256) {
            int a = e / 384, rem = e - a * 384;
            int b = rem >> 6, ds = rem & 63;
            int d = ds >> 3, so = ds & 7;
            C2[a][b][ds] = coefs[d * 552 + so * 69 + 16 + a * 6 + b];
        }
        __syncthreads();
        int r = blockIdx.x * 256 + t;           // 0..2047
        int n = r >> 10, tt = r & 1023;
        float acc[48];
#pragma unroll
        for (int q = 0; q < 48; ++q) acc[q] = 0.f;
#pragma unroll
        for (int a = 0; a < 6; ++a) {
            float vd[8];
#pragma unroll
            for (int d = 0; d < 8; ++d) vd[d] = g_r2[a][n * 8 + d][tt];
#pragma unroll
            for (int b = 0; b < 6; ++b)
#pragma unroll
                for (int so = 0; so < 8; ++so) {
                    float s = 0.f;
#pragma unroll
                    for (int d = 0; d < 8; ++d) s += C2[a][b][d * 8 + so] * vd[d];
                    acc[b * 8 + so] += s;
                }
        }
#pragma unroll
        for (int b = 0; b < 5; ++b)
#pragma unroll
            for (int so = 0; so < 8; ++so)
                g_g2[b][n][so][tt] = acc[b * 8 + so];
        // b=5 (kl): fold into V1 = g3_ikl + g2_kl, broadcast over i
#pragma unroll
        for (int so = 0; so < 8; ++so) {
            float g25 = acc[5 * 8 + so];
            const float* src = &g_g3[2][n][so][0];
            float* dst = &g_V1[n][so][0];
            for (int i = 0; i < 32; ++i)
                dst[i * N2 + tt] = g25 + __ldg(src + i * N2 + tt);
        }
    } else {
        __shared__ float C1[4][4][64];
        __shared__ float sr1[4][16][32];
        for (int e = t; e < 1024; e += 256) {
            int a = e >> 8, b = (e >> 6) & 3, ds = e & 63;
            int d = ds >> 3, so = ds & 7;
            C1[a][b][ds] = coefs[d * 552 + so * 69 + a * 4 + b];
        }
        // r1 (2048 values, 8 per thread)
        for (int q = t; q < 2048; q += 256) {
            int z = q >> 9, mm = (q >> 5) & 15, v = q & 31;
            float s = 0.f;
            if (z == 0) {
#pragma unroll
                for (int u = 0; u < 32; ++u) s += g_r2[0][mm][v * 32 + u];   // r_i
            } else if (z == 1) {
#pragma unroll
                for (int u = 0; u < 32; ++u) s += g_r2[0][mm][u * 32 + v];   // r_j
            } else if (z == 2) {
#pragma unroll
                for (int u = 0; u < 32; ++u) s += g_r2[1][mm][u * 32 + v];   // r_k
            } else {
#pragma unroll
                for (int u = 0; u < 32; ++u) s += g_r2[5][mm][u * 32 + v];   // r_l
            }
            sr1[z][mm][v] = s;
        }
        __syncthreads();
        if (t < 64) {
            int n = t >> 5, v = t & 31;
            float acc[32];
#pragma unroll
            for (int q = 0; q < 32; ++q) acc[q] = 0.f;
#pragma unroll
            for (int a = 0; a < 4; ++a) {
                float vd[8];
#pragma unroll
                for (int d = 0; d < 8; ++d) vd[d] = sr1[a][n * 8 + d][v];
#pragma unroll
                for (int b = 0; b < 4; ++b)
#pragma unroll
                    for (int so = 0; so < 8; ++so) {
                        float s = 0.f;
#pragma unroll
                        for (int d = 0; d < 8; ++d) s += C1[a][b][d * 8 + so] * vd[d];
                        acc[b * 8 + so] += s;
                    }
            }
#pragma unroll
            for (int b = 0; b < 4; ++b)
#pragma unroll
                for (int so = 0; so < 8; ++so)
                    g_g1[b][n][so][v] = acc[b * 8 + so];
        }
    }
}

// ---------------------------------------------------------------------------
// Kf: final assembly. Block per (n,i,j). Only 2 big-table loads per element.
// out = P[so][k] + Q[so][l] + V1[i,k,l] + g3_jkl[j,k,l] + sum_d c4*x
// ---------------------------------------------------------------------------
__global__ void __launch_bounds__(256) k_final(const float* __restrict__ x,
                                               const float* __restrict__ coefs,
                                               const float* __restrict__ bias,
                                               float* __restrict__ out) {
    int bid = blockIdx.x;
    int n = bid >> 10, i = (bid >> 5) & 31, j = bid & 31;
    int t = threadIdx.x, k = t >> 3, lq = t & 7;

    __shared__ float P[8][32], Q[8][32], cf[8][8];
    if (t < 64) cf[t >> 3][t & 7] = coefs[(t >> 3) * 552 + (t & 7) * 69 + 68];
    {
        int so = t >> 5, kk = t & 31, ij = i * 32 + j;
        P[so][kk] = g_g3[0][n][so][ij * 32 + kk]
                  + g_g2[1][n][so][i * 32 + kk]
                  + g_g2[3][n][so][j * 32 + kk]
                  + g_g1[2][n][so][kk]
                  + g_g2[0][n][so][ij]
                  + g_g1[0][n][so][i]
                  + g_g1[1][n][so][j]
                  + bias[so];
        Q[so][kk] = g_g3[1][n][so][ij * 32 + kk]
                  + g_g2[2][n][so][i * 32 + kk]
                  + g_g2[4][n][so][j * 32 + kk]
                  + g_g1[3][n][so][kk];
    }
    __syncthreads();

    int plane = (i * 32 + j) * 256 + t;
    const float4* xb = reinterpret_cast<const float4*>(x);
    float4* ob = reinterpret_cast<float4*>(out);

    float4 xv[8];
#pragma unroll
    for (int d = 0; d < 8; ++d)
        xv[d] = __ldg(xb + (size_t)(n * 8 + d) * (N4 / 4) + plane);

#pragma unroll
    for (int so = 0; so < 8; ++so) {
        float4 v1 = __ldg(reinterpret_cast<const float4*>(g_V1[n][so]) + i * 256 + t);
        float4 a4 = __ldg(reinterpret_cast<const float4*>(g_g3[3][n][so]) + j * 256 + t);
        float base = P[so][k];
        float4 q = *reinterpret_cast<const float4*>(&Q[so][lq * 4]);

        float4 acc;
        acc.x = base + q.x + v1.x + a4.x;
        acc.y = base + q.y + v1.y + a4.y;
        acc.z = base + q.z + v1.z + a4.z;
        acc.w = base + q.w + v1.w + a4.w;
#pragma unroll
        for (int d = 0; d < 8; ++d) {
            float c = cf[d][so];
            acc.x += c * xv[d].x;
            acc.y += c * xv[d].y;
            acc.z += c * xv[d].z;
            acc.w += c * xv[d].w;
        }
        ob[(size_t)(n * 8 + so) * (N4 / 4) + plane] = acc;
    }
}

extern "C" void kernel_launch(void* const* d_in, const int* in_sizes, int n_in,
                              void* d_out, int out_size) {
    const float* x     = (const float*)d_in[0];
    const float* coefs = (const float*)d_in[1];
    const float* bias  = (const float*)d_in[2];
    float* out = (float*)d_out;

    k_pass1<<<512, 256>>>(x);            // r3[0..2], r2[ij], r2[ik]
    k_pass2<<<256, 256>>>(x, coefs);     // r3[3] + all g3 tables
    k_small1<<<256, 256>>>();            // r2[il,jk,jl,kl]
    k_small2<<<9, 256>>>(coefs);         // g2, g1, V1 fold
    k_final<<<2048, 256>>>(x, coefs, bias, out);
}

// round 3
// speedup vs baseline: 1.3139x; 1.1703x over previous
#include <cuda_runtime.h>

#define NV 32
#define N2 1024
#define N3 32768
#define N4 1048576
#define MB 16   // n*d = 2*8
#define SOUT 8

// Scratch (static device memory; no allocation).
// r3 kept-axes order: 0=(i,j,k) 1=(i,j,l) 2=(i,k,l) 3=(j,k,l)
__device__ __align__(16) float g_r3[4][MB][N3];
// r2 order: 0=(i,j) 1=(i,k) 2=(i,l) 3=(j,k) 4=(j,l) 5=(k,l)
__device__ __align__(16) float g_r2[6][MB][N2];
// channel-mixed B-grouped tables
__device__ __align__(16) float g_g3[4][2][SOUT][N3];
__device__ __align__(16) float g_g2[6][2][SOUT][N2];
__device__ __align__(16) float g_g1[4][2][SOUT][NV];

// ---------------------------------------------------------------------------
// K1: block per (m,i). ONE pass over x[m,i,:,:,:], ONE __syncthreads.
// Produces r3[0]=r_ijk, r3[1]=r_ijl, r3[2]=r_ikl, r2[0]=r_ij, r2[1]=r_ik.
// ---------------------------------------------------------------------------
__global__ void __launch_bounds__(256) k_pass1(const float* __restrict__ x) {
    int m = blockIdx.x >> 5, i = blockIdx.x & 31;
    int t = threadIdx.x, w = t >> 5, lane = t & 31;
    int l4 = lane & 7;

    __shared__ float4 scol[8][32][8];   // [w][j][l4] per-warp column partials (32KB)
    __shared__ float  srow[32][32];     // [j][k] row sums (4KB)
    __shared__ float  sij[32][8];       // [j][w] plane partials (1KB)

    float4 acc; acc.x = acc.y = acc.z = acc.w = 0.f;
    float accIK = 0.f;
    const float4* xb = reinterpret_cast<const float4*>(x) + (size_t)(m * 32 + i) * (N3 / 4);

    for (int jo = 0; jo < 32; jo += 4) {
        float4 vv[4];
#pragma unroll
        for (int u = 0; u < 4; ++u) vv[u] = __ldg(xb + (jo + u) * 256 + t);
#pragma unroll
        for (int u = 0; u < 4; ++u) {
            int j = jo + u;
            float4 v = vv[u];
            acc.x += v.x; acc.y += v.y; acc.z += v.z; acc.w += v.w;

            // row sum over l (8-lane groups share one k)
            float s = v.x + v.y + v.z + v.w;
            s += __shfl_down_sync(0xffffffffu, s, 4, 8);
            s += __shfl_down_sync(0xffffffffu, s, 2, 8);
            s += __shfl_down_sync(0xffffffffu, s, 1, 8);
            if (l4 == 0) { srow[j][t >> 3] = s; accIK += s; }

            // plane partial (per warp): sum the 4 row sums (lanes 0,8,16,24)
            float p = s;
            p += __shfl_down_sync(0xffffffffu, p, 16);
            p += __shfl_down_sync(0xffffffffu, p, 8);
            if (lane == 0) sij[j][w] = p;

            // column partial: sum over this warp's 4 k values
            float4 c = v;
            c.x += __shfl_xor_sync(0xffffffffu, c.x, 8);
            c.y += __shfl_xor_sync(0xffffffffu, c.y, 8);
            c.z += __shfl_xor_sync(0xffffffffu, c.z, 8);
            c.w += __shfl_xor_sync(0xffffffffu, c.w, 8);
            c.x += __shfl_xor_sync(0xffffffffu, c.x, 16);
            c.y += __shfl_xor_sync(0xffffffffu, c.y, 16);
            c.z += __shfl_xor_sync(0xffffffffu, c.z, 16);
            c.w += __shfl_xor_sync(0xffffffffu, c.w, 16);
            if (lane < 8) scol[w][j][lane] = c;
        }
    }
    __syncthreads();

    // r_ikl (complete: summed over j in registers)
    reinterpret_cast<float4*>(g_r3[2][m])[i * 256 + t] = acc;
    // r_ijk from srow (coalesced)
    reinterpret_cast<float4*>(g_r3[0][m] + i * N2)[t] = reinterpret_cast<float4*>(srow)[t];
    // r_ijl: combine the 8 per-warp column partials
    {
        int j = t >> 3, q = t & 7;
        float4 rv = scol[0][j][q];
#pragma unroll
        for (int ww = 1; ww < 8; ++ww) {
            float4 cc = scol[ww][j][q];
            rv.x += cc.x; rv.y += cc.y; rv.z += cc.z; rv.w += cc.w;
        }
        reinterpret_cast<float4*>(g_r3[1][m] + i * N2)[t] = rv;
    }
    // r_ij
    if (t < 32) {
        float s = 0.f;
#pragma unroll
        for (int ww = 0; ww < 8; ++ww) s += sij[t][ww];
        g_r2[0][m][i * 32 + t] = s;
    }
    // r_ik
    if (l4 == 0) g_r2[1][m][i * 32 + (t >> 3)] = accIK;
}

// ---------------------------------------------------------------------------
// K2: second x pass. Thread per (n, tt=(j,k,l)). Computes r_jkl on the fly,
// writes it raw, and produces ALL FOUR g3 tables (channel mix) in one shot.
// ---------------------------------------------------------------------------
__global__ void __launch_bounds__(256) k_pass2(const float* __restrict__ x,
                                               const float* __restrict__ coefs) {
    __shared__ float C[4][4][64];   // [A][B][d*8+so]
    int t = threadIdx.x;
    for (int e = t; e < 1024; e += 256) {
        int a = e >> 8, b = (e >> 6) & 3, ds = e & 63;
        int d = ds >> 3, so = ds & 7;
        C[a][b][ds] = coefs[d * 552 + so * 69 + 52 + a * 4 + b];
    }
    __syncthreads();

    int g = blockIdx.x * 256 + t;
    int n = g >> 15, tt = g & 32767;
    const float* xb = x + (size_t)n * 8 * N4 + tt;

    float rj[8];
#pragma unroll
    for (int d = 0; d < 8; ++d) rj[d] = 0.f;
#pragma unroll 4
    for (int i = 0; i < 32; ++i) {
#pragma unroll
        for (int d = 0; d < 8; ++d)
            rj[d] += __ldg(xb + (size_t)d * N4 + i * N3);
    }
#pragma unroll
    for (int d = 0; d < 8; ++d) g_r3[3][n * 8 + d][tt] = rj[d];

    float acc[32];
#pragma unroll
    for (int q = 0; q < 32; ++q) acc[q] = 0.f;
#pragma unroll
    for (int a = 0; a < 4; ++a) {
        float vd[8];
#pragma unroll
        for (int d = 0; d < 8; ++d)
            vd[d] = (a == 3) ? rj[d] : __ldg(&g_r3[a][n * 8 + d][tt]);
#pragma unroll
        for (int b = 0; b < 4; ++b)
#pragma unroll
            for (int so = 0; so < 8; ++so) {
                float s = 0.f;
#pragma unroll
                for (int d = 0; d < 8; ++d) s += C[a][b][d * 8 + so] * vd[d];
                acc[b * 8 + so] += s;
            }
    }
#pragma unroll
    for (int b = 0; b < 4; ++b)
#pragma unroll
        for (int so = 0; so < 8; ++so)
            g_g3[b][n][so][tt] = acc[b * 8 + so];
}

// ---------------------------------------------------------------------------
// S1: remaining rank-2 reductions, all sourced from pass1 outputs:
//   r_il = sum_j r3[1],  r_jk = sum_i r3[0],  r_jl = sum_i r3[1],
//   r_kl = sum_i r3[2]
// ---------------------------------------------------------------------------
__global__ void __launch_bounds__(256) k_small1(void) {
    int g = blockIdx.x * 256 + threadIdx.x;     // 0..65535
    int z = g >> 14, r = g & 16383;
    int m = r >> 10, tt = r & 1023, a = tt >> 5, c = tt & 31;

    const float* p; int strd;
    switch (z) {
        case 0:  p = g_r3[1][m] + a * N2 + c;  strd = 32;   break;  // r_il
        case 1:  p = g_r3[0][m] + a * 32 + c;  strd = N2;   break;  // r_jk
        case 2:  p = g_r3[1][m] + a * 32 + c;  strd = N2;   break;  // r_jl
        default: p = g_r3[2][m] + a * 32 + c;  strd = N2;   break;  // r_kl
    }
    float s = 0.f;
#pragma unroll
    for (int u = 0; u < 32; ++u) s += __ldg(p + u * strd);
    g_r2[z + 2][m][tt] = s;
}

// ---------------------------------------------------------------------------
// S2: blocks 0..7: g2 channel mix; block 8: r1 + g1.
// ---------------------------------------------------------------------------
__global__ void __launch_bounds__(256) k_small2(const float* __restrict__ coefs) {
    int t = threadIdx.x;
    if (blockIdx.x < 8) {
        __shared__ float C2[6][6][64];
        for (int e = t; e < 2304; e += 256) {
            int a = e / 384, rem = e - a * 384;
            int b = rem >> 6, ds = rem & 63;
            int d = ds >> 3, so = ds & 7;
            C2[a][b][ds] = coefs[d * 552 + so * 69 + 16 + a * 6 + b];
        }
        __syncthreads();
        int r = blockIdx.x * 256 + t;           // 0..2047
        int n = r >> 10, tt = r & 1023;
        float acc[48];
#pragma unroll
        for (int q = 0; q < 48; ++q) acc[q] = 0.f;
#pragma unroll
        for (int a = 0; a < 6; ++a) {
            float vd[8];
#pragma unroll
            for (int d = 0; d < 8; ++d) vd[d] = g_r2[a][n * 8 + d][tt];
#pragma unroll
            for (int b = 0; b < 6; ++b)
#pragma unroll
                for (int so = 0; so < 8; ++so) {
                    float s = 0.f;
#pragma unroll
                    for (int d = 0; d < 8; ++d) s += C2[a][b][d * 8 + so] * vd[d];
                    acc[b * 8 + so] += s;
                }
        }
#pragma unroll
        for (int b = 0; b < 6; ++b)
#pragma unroll
            for (int so = 0; so < 8; ++so)
                g_g2[b][n][so][tt] = acc[b * 8 + so];
    } else {
        __shared__ float C1[4][4][64];
        __shared__ float sr1[4][16][32];
        for (int e = t; e < 1024; e += 256) {
            int a = e >> 8, b = (e >> 6) & 3, ds = e & 63;
            int d = ds >> 3, so = ds & 7;
            C1[a][b][ds] = coefs[d * 552 + so * 69 + a * 4 + b];
        }
        // r1 (2048 values, 8 per thread)
        for (int q = t; q < 2048; q += 256) {
            int z = q >> 9, mm = (q >> 5) & 15, v = q & 31;
            float s = 0.f;
            if (z == 0) {
#pragma unroll
                for (int u = 0; u < 32; ++u) s += g_r2[0][mm][v * 32 + u];   // r_i
            } else if (z == 1) {
#pragma unroll
                for (int u = 0; u < 32; ++u) s += g_r2[0][mm][u * 32 + v];   // r_j
            } else if (z == 2) {
#pragma unroll
                for (int u = 0; u < 32; ++u) s += g_r2[1][mm][u * 32 + v];   // r_k
            } else {
#pragma unroll
                for (int u = 0; u < 32; ++u) s += g_r2[5][mm][u * 32 + v];   // r_l
            }
            sr1[z][mm][v] = s;
        }
        __syncthreads();
        if (t < 64) {
            int n = t >> 5, v = t & 31;
            float acc[32];
#pragma unroll
            for (int q = 0; q < 32; ++q) acc[q] = 0.f;
#pragma unroll
            for (int a = 0; a < 4; ++a) {
                float vd[8];
#pragma unroll
                for (int d = 0; d < 8; ++d) vd[d] = sr1[a][n * 8 + d][v];
#pragma unroll
                for (int b = 0; b < 4; ++b)
#pragma unroll
                    for (int so = 0; so < 8; ++so) {
                        float s = 0.f;
#pragma unroll
                        for (int d = 0; d < 8; ++d) s += C1[a][b][d * 8 + so] * vd[d];
                        acc[b * 8 + so] += s;
                    }
            }
#pragma unroll
            for (int b = 0; b < 4; ++b)
#pragma unroll
                for (int so = 0; so < 8; ++so)
                    g_g1[b][n][so][v] = acc[b * 8 + so];
        }
    }
}

// ---------------------------------------------------------------------------
// Kf: final assembly. Block per (n, i, j-quad); loops 8 j's.
// Stages sV[so][kl] = g3_ikl + g2_kl once (reused x8), i-only P/Q parts once.
// ---------------------------------------------------------------------------
__global__ void __launch_bounds__(256, 2) k_final(const float* __restrict__ x,
                                                  const float* __restrict__ coefs,
                                                  const float* __restrict__ bias,
                                                  float* __restrict__ out) {
    int bid = blockIdx.x;
    int n = bid >> 7, i = (bid >> 2) & 31, jq = bid & 3;
    int t = threadIdx.x, k = t >> 3, lq = t & 7;

    __shared__ float4 sV[8][256];          // staged g3_ikl(i) + g2_kl  (32KB)
    __shared__ float  sPi[8][32], sQi[8][32];
    __shared__ float  P[8][32], Q[8][32], cf[8][8];

    // ---- per-block staging ----
#pragma unroll
    for (int so = 0; so < 8; ++so) {
        float4 a = __ldg(reinterpret_cast<const float4*>(g_g3[2][n][so]) + i * 256 + t);
        float4 b = __ldg(reinterpret_cast<const float4*>(g_g2[5][n][so]) + t);
        a.x += b.x; a.y += b.y; a.z += b.z; a.w += b.w;
        sV[so][t] = a;
    }
    if (t < 64) cf[t >> 3][t & 7] = coefs[(t >> 3) * 552 + (t & 7) * 69 + 68];
    {
        int so = t >> 5, kk = t & 31;
        sPi[so][kk] = g_g2[1][n][so][i * 32 + kk] + g_g1[2][n][so][kk]
                    + g_g1[0][n][so][i] + bias[so];
        sQi[so][kk] = g_g2[2][n][so][i * 32 + kk] + g_g1[3][n][so][kk];
    }

    const float4* xb = reinterpret_cast<const float4*>(x);
    float4* ob = reinterpret_cast<float4*>(out);

    for (int jj = 0; jj < 8; ++jj) {
        int j = jq * 8 + jj;
        int ij = i * 32 + j;
        __syncthreads();   // prev iteration consumers done / staging visible
        {
            int so = t >> 5, kk = t & 31;
            float pj = g_g2[0][n][so][ij] + g_g1[1][n][so][j];
            P[so][kk] = sPi[so][kk] + g_g3[0][n][so][ij * 32 + kk]
                      + g_g2[3][n][so][j * 32 + kk] + pj;
            Q[so][kk] = sQi[so][kk] + g_g3[1][n][so][ij * 32 + kk]
                      + g_g2[4][n][so][j * 32 + kk];
        }

        int plane = ij * 256 + t;
        float4 xv[8];
#pragma unroll
        for (int d = 0; d < 8; ++d)
            xv[d] = __ldg(xb + (size_t)(n * 8 + d) * (N4 / 4) + plane);
        float4 a4[8];
#pragma unroll
        for (int so = 0; so < 8; ++so)
            a4[so] = __ldg(reinterpret_cast<const float4*>(g_g3[3][n][so]) + j * 256 + t);

        __syncthreads();   // P/Q ready

#pragma unroll
        for (int so = 0; so < 8; ++so) {
            float4 v1 = sV[so][t];
            float base = P[so][k];
            float4 q = *reinterpret_cast<const float4*>(&Q[so][lq * 4]);

            float4 acc;
            acc.x = base + q.x + v1.x + a4[so].x;
            acc.y = base + q.y + v1.y + a4[so].y;
            acc.z = base + q.z + v1.z + a4[so].z;
            acc.w = base + q.w + v1.w + a4[so].w;
#pragma unroll
            for (int d = 0; d < 8; ++d) {
                float c = cf[d][so];
                acc.x += c * xv[d].x;
                acc.y += c * xv[d].y;
                acc.z += c * xv[d].z;
                acc.w += c * xv[d].w;
            }
            ob[(size_t)(n * 8 + so) * (N4 / 4) + plane] = acc;
        }
    }
}

extern "C" void kernel_launch(void* const* d_in, const int* in_sizes, int n_in,
                              void* d_out, int out_size) {
    const float* x     = (const float*)d_in[0];
    const float* coefs = (const float*)d_in[1];
    const float* bias  = (const float*)d_in[2];
    float* out = (float*)d_out;

    k_pass1<<<512, 256>>>(x);            // r3[0..2], r2[ij], r2[ik]
    k_small1<<<256, 256>>>();            // r2[il,jk,jl,kl] (from pass1 outputs)
    k_pass2<<<256, 256>>>(x, coefs);     // r3[3] + all g3 tables
    k_small2<<<9, 256>>>(coefs);         // g2, g1
    k_final<<<256, 256>>>(x, coefs, bias, out);
}

// round 4
// speedup vs baseline: 1.5002x; 1.1418x over previous
#include <cuda_runtime.h>

#define NV 32
#define N2 1024
#define N3 32768
#define N4 1048576
#define MB 16   // n*d = 2*8
#define SOUT 8

// Scratch (static device memory; no allocation).
// r3 kept-axes order: 0=(i,j,k) 1=(i,j,l) 2=(i,k,l) 3=(j,k,l)
__device__ __align__(16) float g_r3[4][MB][N3];
// r2 order: 0=(i,j) 1=(i,k) 2=(i,l) 3=(j,k) 4=(j,l) 5=(k,l)
__device__ __align__(16) float g_r2[6][MB][N2];
// channel-mixed B-grouped tables
__device__ __align__(16) float g_g3[4][2][SOUT][N3];
__device__ __align__(16) float g_g2[6][2][SOUT][N2];
__device__ __align__(16) float g_g1[4][2][SOUT][NV];

// ---------------------------------------------------------------------------
// K1: block per (m,i). ONE pass over x[m,i,:,:,:], ONE __syncthreads.
// Produces r3[0]=r_ijk, r3[1]=r_ijl, r3[2]=r_ikl, r2[0]=r_ij, r2[1]=r_ik.
// ---------------------------------------------------------------------------
__global__ void __launch_bounds__(256) k_pass1(const float* __restrict__ x) {
    int m = blockIdx.x >> 5, i = blockIdx.x & 31;
    int t = threadIdx.x, w = t >> 5, lane = t & 31;
    int l4 = lane & 7;

    __shared__ float4 scol[8][32][8];   // [w][j][l4] per-warp column partials (32KB)
    __shared__ float  srow[32][32];     // [j][k] row sums (4KB)
    __shared__ float  sij[32][8];       // [j][w] plane partials (1KB)

    float4 acc; acc.x = acc.y = acc.z = acc.w = 0.f;
    float accIK = 0.f;
    const float4* xb = reinterpret_cast<const float4*>(x) + (size_t)(m * 32 + i) * (N3 / 4);

    for (int jo = 0; jo < 32; jo += 4) {
        float4 vv[4];
#pragma unroll
        for (int u = 0; u < 4; ++u) vv[u] = __ldg(xb + (jo + u) * 256 + t);
#pragma unroll
        for (int u = 0; u < 4; ++u) {
            int j = jo + u;
            float4 v = vv[u];
            acc.x += v.x; acc.y += v.y; acc.z += v.z; acc.w += v.w;

            float s = v.x + v.y + v.z + v.w;
            s += __shfl_down_sync(0xffffffffu, s, 4, 8);
            s += __shfl_down_sync(0xffffffffu, s, 2, 8);
            s += __shfl_down_sync(0xffffffffu, s, 1, 8);
            if (l4 == 0) { srow[j][t >> 3] = s; accIK += s; }

            float p = s;
            p += __shfl_down_sync(0xffffffffu, p, 16);
            p += __shfl_down_sync(0xffffffffu, p, 8);
            if (lane == 0) sij[j][w] = p;

            float4 c = v;
            c.x += __shfl_xor_sync(0xffffffffu, c.x, 8);
            c.y += __shfl_xor_sync(0xffffffffu, c.y, 8);
            c.z += __shfl_xor_sync(0xffffffffu, c.z, 8);
            c.w += __shfl_xor_sync(0xffffffffu, c.w, 8);
            c.x += __shfl_xor_sync(0xffffffffu, c.x, 16);
            c.y += __shfl_xor_sync(0xffffffffu, c.y, 16);
            c.z += __shfl_xor_sync(0xffffffffu, c.z, 16);
            c.w += __shfl_xor_sync(0xffffffffu, c.w, 16);
            if (lane < 8) scol[w][j][lane] = c;
        }
    }
    __syncthreads();

    reinterpret_cast<float4*>(g_r3[2][m])[i * 256 + t] = acc;
    reinterpret_cast<float4*>(g_r3[0][m] + i * N2)[t] = reinterpret_cast<float4*>(srow)[t];
    {
        int j = t >> 3, q = t & 7;
        float4 rv = scol[0][j][q];
#pragma unroll
        for (int ww = 1; ww < 8; ++ww) {
            float4 cc = scol[ww][j][q];
            rv.x += cc.x; rv.y += cc.y; rv.z += cc.z; rv.w += cc.w;
        }
        reinterpret_cast<float4*>(g_r3[1][m] + i * N2)[t] = rv;
    }
    if (t < 32) {
        float s = 0.f;
#pragma unroll
        for (int ww = 0; ww < 8; ++ww) s += sij[t][ww];
        g_r2[0][m][i * 32 + t] = s;
    }
    if (l4 == 0) g_r2[1][m][i * 32 + (t >> 3)] = accIK;
}

// ---------------------------------------------------------------------------
// K2: second x pass (float2). Thread per (n, 2 consecutive tt). Computes
// r_jkl on the fly and produces all four g3 tables in one shot.
// ---------------------------------------------------------------------------
__global__ void __launch_bounds__(256) k_pass2(const float* __restrict__ x,
                                               const float* __restrict__ coefs) {
    __shared__ float C[4][4][64];   // [A][B][d*8+so]
    int t = threadIdx.x;
    for (int e = t; e < 1024; e += 256) {
        int a = e >> 8, b = (e >> 6) & 3, ds = e & 63;
        int d = ds >> 3, so = ds & 7;
        C[a][b][ds] = coefs[d * 552 + so * 69 + 52 + a * 4 + b];
    }
    __syncthreads();

    int g = blockIdx.x * 256 + t;             // 0..32767
    int n = g >> 14, tt2 = g & 16383;         // float2 index into N3/2
    const float2* xb = reinterpret_cast<const float2*>(x) + (size_t)n * 8 * (N4 / 2) + tt2;

    float2 rj[8];
#pragma unroll
    for (int d = 0; d < 8; ++d) { rj[d].x = 0.f; rj[d].y = 0.f; }
#pragma unroll 4
    for (int i = 0; i < 32; ++i) {
#pragma unroll
        for (int d = 0; d < 8; ++d) {
            float2 v = __ldg(xb + (size_t)d * (N4 / 2) + i * (N3 / 2));
            rj[d].x += v.x; rj[d].y += v.y;
        }
    }
#pragma unroll
    for (int d = 0; d < 8; ++d)
        reinterpret_cast<float2*>(g_r3[3][n * 8 + d])[tt2] = rj[d];

    float2 acc[32];
#pragma unroll
    for (int q = 0; q < 32; ++q) { acc[q].x = 0.f; acc[q].y = 0.f; }
#pragma unroll
    for (int a = 0; a < 4; ++a) {
        float2 vd[8];
#pragma unroll
        for (int d = 0; d < 8; ++d)
            vd[d] = (a == 3) ? rj[d]
                  : __ldg(reinterpret_cast<const float2*>(g_r3[a][n * 8 + d]) + tt2);
#pragma unroll
        for (int b = 0; b < 4; ++b)
#pragma unroll
            for (int so = 0; so < 8; ++so) {
                float sx = 0.f, sy = 0.f;
#pragma unroll
                for (int d = 0; d < 8; ++d) {
                    float c = C[a][b][d * 8 + so];
                    sx += c * vd[d].x; sy += c * vd[d].y;
                }
                acc[b * 8 + so].x += sx; acc[b * 8 + so].y += sy;
            }
    }
#pragma unroll
    for (int b = 0; b < 4; ++b)
#pragma unroll
        for (int so = 0; so < 8; ++so)
            reinterpret_cast<float2*>(g_g3[b][n][so])[tt2] = acc[b * 8 + so];
}

// ---------------------------------------------------------------------------
// S1: remaining rank-2 reductions from pass1 outputs.
// ---------------------------------------------------------------------------
__global__ void __launch_bounds__(256) k_small1(void) {
    int g = blockIdx.x * 256 + threadIdx.x;     // 0..65535
    int z = g >> 14, r = g & 16383;
    int m = r >> 10, tt = r & 1023, a = tt >> 5, c = tt & 31;

    const float* p; int strd;
    switch (z) {
        case 0:  p = g_r3[1][m] + a * N2 + c;  strd = 32;   break;  // r_il
        case 1:  p = g_r3[0][m] + a * 32 + c;  strd = N2;   break;  // r_jk
        case 2:  p = g_r3[1][m] + a * 32 + c;  strd = N2;   break;  // r_jl
        default: p = g_r3[2][m] + a * 32 + c;  strd = N2;   break;  // r_kl
    }
    float s = 0.f;
#pragma unroll
    for (int u = 0; u < 32; ++u) s += __ldg(p + u * strd);
    g_r2[z + 2][m][tt] = s;
}

// ---------------------------------------------------------------------------
// S2: blocks 0..63: g2 channel mix (thread = (tt_local, so), 6 b-outputs in
// registers, coefficients as float4 pairs). Block 64: r1 + g1.
// ---------------------------------------------------------------------------
__global__ void __launch_bounds__(256) k_small2(const float* __restrict__ coefs) {
    int t = threadIdx.x;
    if (blockIdx.x < 64) {
        int n = blockIdx.x >> 5, tb = (blockIdx.x & 31) * 32;
        __shared__ float4 CT[6][8][8][2];   // [a][d][so][{b0..3},{b4,b5,0,0}]
        __shared__ float r2v[6][8][32];     // [a][d][tt_local]
        for (int e = t; e < 3072; e += 256) {
            int a = e >> 9, r = e & 511;
            int d = r >> 6, so = (r >> 3) & 7, bq = r & 7;
            reinterpret_cast<float*>(CT)[((a * 8 + d) * 8 + so) * 8 + bq] =
                (bq < 6) ? coefs[d * 552 + so * 69 + 16 + a * 6 + bq] : 0.f;
        }
        for (int e = t; e < 1536; e += 256) {
            int a = e >> 8, r = e & 255;
            int d = r >> 5, c = r & 31;
            r2v[a][d][c] = g_r2[a][n * 8 + d][tb + c];
        }
        __syncthreads();

        int tl = t >> 3, so = t & 7;
        float b0 = 0.f, b1 = 0.f, b2 = 0.f, b3 = 0.f, b4 = 0.f, b5 = 0.f;
#pragma unroll
        for (int a = 0; a < 6; ++a)
#pragma unroll
            for (int d = 0; d < 8; ++d) {
                float v = r2v[a][d][tl];
                float4 c0 = CT[a][d][so][0];
                float4 c1 = CT[a][d][so][1];
                b0 += v * c0.x; b1 += v * c0.y; b2 += v * c0.z;
                b3 += v * c0.w; b4 += v * c1.x; b5 += v * c1.y;
            }
        int tt = tb + tl;
        g_g2[0][n][so][tt] = b0; g_g2[1][n][so][tt] = b1;
        g_g2[2][n][so][tt] = b2; g_g2[3][n][so][tt] = b3;
        g_g2[4][n][so][tt] = b4; g_g2[5][n][so][tt] = b5;
    } else {
        __shared__ float C1[4][4][64];
        __shared__ float sr1[4][16][32];
        for (int e = t; e < 1024; e += 256) {
            int a = e >> 8, b = (e >> 6) & 3, ds = e & 63;
            int d = ds >> 3, so = ds & 7;
            C1[a][b][ds] = coefs[d * 552 + so * 69 + a * 4 + b];
        }
        for (int q = t; q < 2048; q += 256) {
            int z = q >> 9, mm = (q >> 5) & 15, v = q & 31;
            float s = 0.f;
            if (z == 0) {
#pragma unroll
                for (int u = 0; u < 32; ++u) s += g_r2[0][mm][v * 32 + u];   // r_i
            } else if (z == 1) {
#pragma unroll
                for (int u = 0; u < 32; ++u) s += g_r2[0][mm][u * 32 + v];   // r_j
            } else if (z == 2) {
#pragma unroll
                for (int u = 0; u < 32; ++u) s += g_r2[1][mm][u * 32 + v];   // r_k
            } else {
#pragma unroll
                for (int u = 0; u < 32; ++u) s += g_r2[5][mm][u * 32 + v];   // r_l
            }
            sr1[z][mm][v] = s;
        }
        __syncthreads();
        if (t < 64) {
            int n = t >> 5, v = t & 31;
            float acc[32];
#pragma unroll
            for (int q = 0; q < 32; ++q) acc[q] = 0.f;
#pragma unroll
            for (int a = 0; a < 4; ++a) {
                float vd[8];
#pragma unroll
                for (int d = 0; d < 8; ++d) vd[d] = sr1[a][n * 8 + d][v];
#pragma unroll
                for (int b = 0; b < 4; ++b)
#pragma unroll
                    for (int so = 0; so < 8; ++so) {
                        float s = 0.f;
#pragma unroll
                        for (int d = 0; d < 8; ++d) s += C1[a][b][d * 8 + so] * vd[d];
                        acc[b * 8 + so] += s;
                    }
            }
#pragma unroll
            for (int b = 0; b < 4; ++b)
#pragma unroll
                for (int so = 0; so < 8; ++so)
                    g_g1[b][n][so][v] = acc[b * 8 + so];
        }
    }
}

// ---------------------------------------------------------------------------
// Kf: final assembly. Block per (n, i, j-quad); loops 8 j's with ZERO syncs
// inside the loop: all 8 j's worth of P/Q precomputed, sV staged once.
// Dynamic smem: sV(32KB) + P8(8KB) + Q8(8KB) + cf(256B) = 49408B.
// ---------------------------------------------------------------------------
__global__ void __launch_bounds__(256, 2) k_final(const float* __restrict__ x,
                                                  const float* __restrict__ coefs,
                                                  const float* __restrict__ bias,
                                                  float* __restrict__ out) {
    extern __shared__ __align__(16) char sm[];
    float4* sV = reinterpret_cast<float4*>(sm);                 // [8][256]
    float (*P8)[8][32] = reinterpret_cast<float(*)[8][32]>(sm + 32768);
    float (*Q8)[8][32] = reinterpret_cast<float(*)[8][32]>(sm + 40960);
    float (*cf)[8]     = reinterpret_cast<float(*)[8]>(sm + 49152);

    int bid = blockIdx.x;
    int n = bid >> 7, i = (bid >> 2) & 31, jq = bid & 3;
    int t = threadIdx.x, k = t >> 3, lq = t & 7;

#pragma unroll
    for (int so = 0; so < 8; ++so) {
        float4 a = __ldg(reinterpret_cast<const float4*>(g_g3[2][n][so]) + i * 256 + t);
        float4 b = __ldg(reinterpret_cast<const float4*>(g_g2[5][n][so]) + t);
        a.x += b.x; a.y += b.y; a.z += b.z; a.w += b.w;
        sV[so * 256 + t] = a;
    }
    if (t < 64) cf[t >> 3][t & 7] = coefs[(t >> 3) * 552 + (t & 7) * 69 + 68];
    {
        int jj = t >> 5, kk = t & 31;
        int j = jq * 8 + jj, ij = i * 32 + j;
#pragma unroll
        for (int so = 0; so < 8; ++so) {
            P8[jj][so][kk] = __ldg(&g_g3[0][n][so][ij * 32 + kk])
                           + __ldg(&g_g2[3][n][so][j * 32 + kk])
                           + __ldg(&g_g2[1][n][so][i * 32 + kk])
                           + __ldg(&g_g1[2][n][so][kk])
                           + __ldg(&g_g2[0][n][so][ij])
                           + __ldg(&g_g1[0][n][so][i])
                           + __ldg(&g_g1[1][n][so][j])
                           + __ldg(&bias[so]);
            Q8[jj][so][kk] = __ldg(&g_g3[1][n][so][ij * 32 + kk])
                           + __ldg(&g_g2[4][n][so][j * 32 + kk])
                           + __ldg(&g_g2[2][n][so][i * 32 + kk])
                           + __ldg(&g_g1[3][n][so][kk]);
        }
    }
    __syncthreads();

    const float4* xb = reinterpret_cast<const float4*>(x);
    float4* ob = reinterpret_cast<float4*>(out);

    for (int jj = 0; jj < 8; ++jj) {
        int j = jq * 8 + jj;
        int plane = (i * 32 + j) * 256 + t;

        float4 xv[8];
#pragma unroll
        for (int d = 0; d < 8; ++d)
            xv[d] = __ldg(xb + (size_t)(n * 8 + d) * (N4 / 4) + plane);
        float4 a4[8];
#pragma unroll
        for (int so = 0; so < 8; ++so)
            a4[so] = __ldg(reinterpret_cast<const float4*>(g_g3[3][n][so]) + j * 256 + t);

#pragma unroll
        for (int so = 0; so < 8; ++so) {
            float4 v1 = sV[so * 256 + t];
            float base = P8[jj][so][k];
            float4 q = *reinterpret_cast<const float4*>(&Q8[jj][so][lq * 4]);

            float4 acc;
            acc.x = base + q.x + v1.x + a4[so].x;
            acc.y = base + q.y + v1.y + a4[so].y;
            acc.z = base + q.z + v1.z + a4[so].z;
            acc.w = base + q.w + v1.w + a4[so].w;
#pragma unroll
            for (int d = 0; d < 8; ++d) {
                float c = cf[d][so];
                acc.x += c * xv[d].x;
                acc.y += c * xv[d].y;
                acc.z += c * xv[d].z;
                acc.w += c * xv[d].w;
            }
            ob[(size_t)(n * 8 + so) * (N4 / 4) + plane] = acc;
        }
    }
}

extern "C" void kernel_launch(void* const* d_in, const int* in_sizes, int n_in,
                              void* d_out, int out_size) {
    const float* x     = (const float*)d_in[0];
    const float* coefs = (const float*)d_in[1];
    const float* bias  = (const float*)d_in[2];
    float* out = (float*)d_out;

    cudaFuncSetAttribute(k_final, cudaFuncAttributeMaxDynamicSharedMemorySize, 49408);

    k_pass1<<<512, 256>>>(x);            // r3[0..2], r2[ij], r2[ik]
    k_small1<<<256, 256>>>();            // r2[il,jk,jl,kl]
    k_pass2<<<128, 256>>>(x, coefs);     // r3[3] + all g3 tables
    k_small2<<<65, 256>>>(coefs);        // g2 (64 blocks) + r1/g1 (1 block)
    k_final<<<256, 256, 49408>>>(x, coefs, bias, out);
}